// round 7
// baseline (speedup 1.0000x reference)
#include <cuda_runtime.h>
#include <stdint.h>

namespace {

constexpr int NQ = 14;
constexpr int NS = 1 << NQ;          // 16384 amplitudes
constexpr int NT = 1024;             // threads per CTA (32 warps -> occupancy)

struct Smem {
    float2 st[NS];                    // state, XOR-swizzled layout (no padding)
    float  pbuf[NS];                  // permuted probabilities
    float2 T[7][4];                   // pair tables: prefix circuit per bit-pair
    float pc[21], ps[21];             // slots 0-6 XX2 (cp col 7+s), 7-20 RX3 (qubit s-7)
    float red[(NT / 32) * NQ];
};

__device__ uint16_t g_inv[NS];       // inverse of the composed MCX permutation

__device__ __forceinline__ float2 cmul(float2 a, float2 b) {
    return make_float2(fmaf(a.x, b.x, -a.y * b.y), fmaf(a.x, b.y, a.y * b.x));
}

// XOR-linear swizzled byte offset of float2 element i: conflict-free for all passes,
// and swaddr(a^b) == swaddr(a) ^ swaddr(b)  -> orbit addresses = base ^ const.
__device__ __host__ __forceinline__ uint32_t swaddr(uint32_t i) {
    return (i << 3) ^ ((i >> 1) & 0x78u);
}

__device__ __forceinline__ float2 ld_st(const Smem* sm, uint32_t off) {
    return *reinterpret_cast<const float2*>(reinterpret_cast<const char*>(sm->st) + off);
}
__device__ __forceinline__ void st_st(Smem* sm, uint32_t off, float2 v) {
    *reinterpret_cast<float2*>(reinterpret_cast<char*>(sm->st) + off) = v;
}

// Apply NG butterfly gates; gate g pairs t <-> t^combos[g] (combo = mask over gen dims).
template<int G, int NG>
__device__ __forceinline__ void apply_gates(float2 (&a)[1 << G], const int (&combos)[NG],
                                            const float (&cg)[NG], const float (&sg)[NG]) {
#pragma unroll
    for (int g = 0; g < NG; ++g) {
        const int cb = combos[g];
        const int lb = cb & (-cb);
        const float c = cg[g], s = sg[g];
#pragma unroll
        for (int t = 0; t < (1 << G); ++t) {
            if ((t & lb) == 0) {
                const int u = t ^ cb;
                const float2 a0 = a[t], a1 = a[u];
                a[t] = make_float2(fmaf(c, a0.x,  s * a1.y), fmaf(c, a0.y, -s * a1.x));
                a[u] = make_float2(fmaf(c, a1.x,  s * a0.y), fmaf(c, a1.y, -s * a0.x));
            }
        }
    }
}

// rep formulas as functor structs (no --extended-lambda available)
struct RepB { __device__ __forceinline__ int operator()(int k) const {
    return ((k & 0xF) << 1) | ((k >> 4) << 7);   // non-span bits 1-4, 7-12
}};
struct RepC { __device__ __forceinline__ int operator()(int k) const {
    return (k & 0x1FF) | ((k >> 9) << 13);       // non-span bits 0-8, 13
}};

// Generic load-gates-store pass with caller-provided rep formula (RepF).
template<int G, int NG, class RepF>
__device__ __forceinline__ void run_pass(Smem* sm, RepF repf, const int (&gens)[G],
                                         const int (&combos)[NG], const int (&slots)[NG]) {
    constexpr int NO = 1 << G;
    float cg[NG], sg[NG];
#pragma unroll
    for (int g = 0; g < NG; ++g) { cg[g] = sm->pc[slots[g]]; sg[g] = sm->ps[slots[g]]; }
    for (int k = threadIdx.x; k < (NS >> G); k += NT) {
        const uint32_t abase = swaddr((uint32_t)repf(k));
        float2 a[NO];
#pragma unroll
        for (int t = 0; t < NO; ++t) {
            uint32_t x = 0;
#pragma unroll
            for (int g = 0; g < G; ++g) if ((t >> g) & 1) x ^= (uint32_t)gens[g];
            a[t] = ld_st(sm, abase ^ swaddr(x));
        }
        apply_gates<G, NG>(a, combos, cg, sg);
#pragma unroll
        for (int t = 0; t < NO; ++t) {
            uint32_t x = 0;
#pragma unroll
            for (int g = 0; g < G; ++g) if ((t >> g) & 1) x ^= (uint32_t)gens[g];
            st_st(sm, abase ^ swaddr(x), a[t]);
        }
    }
}

// Pass A: generate state from pair tables + XX(9,10), XX(11,12), RX q9..q12.
__device__ __forceinline__ void run_passA(Smem* sm) {
    // gens: g0=0x18(t0), g1=0x10(t1), g2=0x06(t2), g3=0x04(t3); span bits 1-4
    constexpr int combos[6] = {1, 4, 2, 3, 8, 12};  // XX(9,10),XX(11,12),RX q9,q10,q11,q12
    constexpr int slots[6]  = {4, 5, 16, 17, 18, 19};
    float cg[6], sg[6];
#pragma unroll
    for (int g = 0; g < 6; ++g) { cg[g] = sm->pc[slots[g]]; sg[g] = sm->ps[slots[g]]; }

    for (int k = threadIdx.x; k < (NS >> 4); k += NT) {
        const int rep = (k & 1) | ((k >> 1) << 5);          // non-span bits 0, 5-13
        const uint32_t abase = swaddr((uint32_t)rep);
        // amp(i) = prod_m T_m[(i>>2m)&3]; bits 5-13 fixed by rep
        const float2 base = cmul(cmul(sm->T[3][(rep >> 6) & 3], sm->T[4][(rep >> 8) & 3]),
                                 cmul(sm->T[5][(rep >> 10) & 3], sm->T[6][(rep >> 12) & 3]));
        const int b0 = rep & 1, b5 = (rep >> 5) & 1;
        const float2 q2x[2] = { cmul(base, sm->T[2][2 * b5]),
                                cmul(base, sm->T[2][1 + 2 * b5]) };   // index = bit4
        const float2 q0[2] = { sm->T[0][b0], sm->T[0][b0 + 2] };      // index = bit1
        float2 m8[2][4];
#pragma unroll
        for (int b4 = 0; b4 < 2; ++b4)
#pragma unroll
            for (int j23 = 0; j23 < 4; ++j23)
                m8[b4][j23] = cmul(q2x[b4], sm->T[1][j23]);
        float2 a[16];
#pragma unroll
        for (int t = 0; t < 16; ++t) {
            // in-span bits as functions of t: b1=t2, b2=t2^t3, b3=t0, b4=t0^t1
            const int t0 = t & 1, t1 = (t >> 1) & 1, t2 = (t >> 2) & 1, t3 = (t >> 3) & 1;
            a[t] = cmul(m8[t0 ^ t1][(t0 << 1) | (t2 ^ t3)], q0[t2]);
        }
        apply_gates<4, 6>(a, combos, cg, sg);
#pragma unroll
        for (int t = 0; t < 16; ++t) {
            uint32_t x = 0;
            if (t & 1) x ^= 0x18u;
            if (t & 2) x ^= 0x10u;
            if (t & 4) x ^= 0x06u;
            if (t & 8) x ^= 0x04u;
            st_st(sm, abase ^ swaddr(x), a[t]);
        }
    }
}

// Pass D: XX(5,6) + RX q5,q6, then scatter |amp|^2 into pbuf at permuted index.
__device__ __forceinline__ void run_passD(Smem* sm) {
    constexpr int combos[3] = {1, 2, 3};            // XX(5,6), RX q5, RX q6
    constexpr int slots[3]  = {2, 12, 13};
    constexpr int XT[4] = {0, 0x180, 0x100, 0x080};
    float cg[3], sg[3];
#pragma unroll
    for (int g = 0; g < 3; ++g) { cg[g] = sm->pc[slots[g]]; sg[g] = sm->ps[slots[g]]; }
    for (int k = threadIdx.x; k < (NS >> 2); k += NT) {
        const int rep = (k & 0x7F) | ((k >> 7) << 9);  // non-span bits 0-6, 9-13
        const uint32_t abase = swaddr((uint32_t)rep);
        float2 a[4];
#pragma unroll
        for (int t = 0; t < 4; ++t) a[t] = ld_st(sm, abase ^ swaddr((uint32_t)XT[t]));
        apply_gates<2, 3>(a, combos, cg, sg);
#pragma unroll
        for (int t = 0; t < 4; ++t) {
            const float pr = fmaf(a[t].x, a[t].x, a[t].y * a[t].y);
            const int i = (int)__ldg(&g_inv[rep ^ XT[t]]);
            sm->pbuf[i] = pr;
        }
    }
}

// Pass E: Walsh-style sign-tree reduction, 16 consecutive probs per thread.
__device__ __forceinline__ void run_passE(Smem* sm, float (&acc)[NQ]) {
    const int tid = threadIdx.x;
    float pv[16];
#pragma unroll
    for (int q = 0; q < 4; ++q) {
        const float4 v = reinterpret_cast<const float4*>(sm->pbuf)[tid * 4 + q];
        pv[4 * q + 0] = v.x; pv[4 * q + 1] = v.y; pv[4 * q + 2] = v.z; pv[4 * q + 3] = v.w;
    }
    float D0 = 0.f, D1 = 0.f, D2 = 0.f;
    float s8[8];
#pragma unroll
    for (int i = 0; i < 8; ++i) { s8[i] = pv[2*i] + pv[2*i+1]; D0 += pv[2*i] - pv[2*i+1]; }
    float s4[4];
#pragma unroll
    for (int i = 0; i < 4; ++i) { s4[i] = s8[2*i] + s8[2*i+1]; D1 += s8[2*i] - s8[2*i+1]; }
    float s2a[2];
#pragma unroll
    for (int i = 0; i < 2; ++i) { s2a[i] = s4[2*i] + s4[2*i+1]; D2 += s4[2*i] - s4[2*i+1]; }
    const float S  = s2a[0] + s2a[1];
    const float D3 = s2a[0] - s2a[1];
    acc[13] = D0; acc[12] = D1; acc[11] = D2; acc[10] = D3;
    // bits 4..13 of index j = tid bits 0..9; qubit w = 13 - b
#pragma unroll
    for (int bb = 4; bb <= 13; ++bb)
        acc[13 - bb] = ((tid >> (bb - 4)) & 1) ? -S : S;
}

__global__ void build_inv_kernel() {
    const int i = blockIdx.x * blockDim.x + threadIdx.x;
    int j = i;
#pragma unroll
    for (int w = NQ - 1; w >= 0; --w) {
        const int c1 = NQ - 1 - w;
        const int c2 = NQ - 1 - ((w + 1) % NQ);
        const int tt = NQ - 1 - ((w + 2) % NQ);
        const int b1 = (j >> c1) & 1;
        const int b2 = (j >> c2) & 1;
        if (b1 & (b2 ^ 1)) j ^= (1 << tt);
    }
    g_inv[j] = (uint16_t)i;   // composite(i) = j  =>  inv[j] = i (bijection, no race)
}

__global__ __launch_bounds__(NT, 1)
void qsim_kernel(const float* __restrict__ cp, const float* __restrict__ p,
                 float* __restrict__ out) {
    extern __shared__ char smraw[];
    Smem* sm = reinterpret_cast<Smem*>(smraw);
    const int tid = threadIdx.x;
    const int b = blockIdx.x;

    if (tid < NQ) {
        const int w = tid;
        float sn, cs;
        if (w >= 7) {
            sincosf(0.5f * cp[b * NQ + w], &sn, &cs);
            sm->pc[w - 7] = cs; sm->ps[w - 7] = sn;
        }
        sincosf(0.5f * p[(b * 3 + 2) * NQ + w], &sn, &cs);
        sm->pc[7 + w] = cs; sm->ps[7 + w] = sn;
    }
    // Pair tables: T_m for bit-pair (2m+1, 2m) = qubit pair (2k, 2k+1), k = 6-m.
    if (tid < 7) {
        const int m = tid, k = 6 - m;
        const int qa = 2 * k, qb = 2 * k + 1;
        float sa, ca, sb, cb, sx, cx;
        sincosf(0.5f * p[(b * 3 + 0) * NQ + qa], &sa, &ca);
        sincosf(0.5f * p[(b * 3 + 0) * NQ + qb], &sb, &cb);
        sincosf(0.5f * cp[b * NQ + k], &sx, &cx);
        float2 v[4] = { make_float2(ca * cb, 0.f), make_float2(0.f, -ca * sb),
                        make_float2(0.f, -sa * cb), make_float2(-sa * sb, 0.f) };
        float2 u[4];
#pragma unroll
        for (int j = 0; j < 4; ++j) {
            const float2 pv = v[j], qv = v[j ^ 3];
            u[j] = make_float2(fmaf(cx, pv.x,  sx * qv.y), fmaf(cx, pv.y, -sx * qv.x));
        }
        const float tza = p[(b * 3 + 1) * NQ + qa];
        const float tzb = p[(b * 3 + 1) * NQ + qb];
#pragma unroll
        for (int j = 0; j < 4; ++j) {
            const float ang = 0.5f * (((j & 2) ? tza : -tza) + ((j & 1) ? tzb : -tzb));
            float se, ce;
            sincosf(ang, &se, &ce);
            sm->T[m][j] = cmul(u[j], make_float2(ce, se));
        }
    }
    __syncthreads();

    run_passA(sm);                                   // generate + XX(9,10),(11,12) + RX q9-12
    __syncthreads();

    {   // Pass B: XX(13,0), RX q0,q13, XX(7,8), RX q7,q8
        constexpr int gens[4] = {0x2001, 0x2000, 0x60, 0x40};
        constexpr int combos[6] = {1, 2, 3, 4, 8, 12};
        constexpr int slots[6]  = {6, 7, 20, 3, 14, 15};
        run_pass<4, 6>(sm, RepB{}, gens, combos, slots);
    }
    __syncthreads();

    {   // Pass C: XX(1,2), RX q1,q2, XX(3,4), RX q3,q4
        constexpr int gens[4] = {0x1800, 0x1000, 0x600, 0x400};
        constexpr int combos[6] = {1, 2, 3, 4, 8, 12};
        constexpr int slots[6]  = {0, 8, 9, 1, 10, 11};
        run_pass<4, 6>(sm, RepC{}, gens, combos, slots);
    }
    __syncthreads();

    run_passD(sm);                                   // XX(5,6)+RX q5,q6 + prob scatter
    __syncthreads();

    float acc[NQ];
    run_passE(sm, acc);                              // sign-tree reduction

#pragma unroll
    for (int w = 0; w < NQ; ++w)
#pragma unroll
        for (int off = 16; off > 0; off >>= 1)
            acc[w] += __shfl_xor_sync(0xffffffffu, acc[w], off);

    const int warp = tid >> 5, lane = tid & 31;
    if (lane == 0) {
#pragma unroll
        for (int w = 0; w < NQ; ++w) sm->red[warp * NQ + w] = acc[w];
    }
    __syncthreads();
    if (tid < NQ) {
        float s = 0.f;
#pragma unroll
        for (int ww = 0; ww < NT / 32; ++ww) s += sm->red[ww * NQ + tid];
        out[b * NQ + tid] = s;
    }
}

} // namespace

extern "C" void kernel_launch(void* const* d_in, const int* in_sizes, int n_in,
                              void* d_out, int out_size) {
    const float* cp = (const float*)d_in[0];
    const float* p  = (const float*)d_in[1];
    float* out = (float*)d_out;
    const int B = in_sizes[0] / NQ;   // 512
    build_inv_kernel<<<NS / 512, 512>>>();
    cudaFuncSetAttribute(qsim_kernel, cudaFuncAttributeMaxDynamicSharedMemorySize,
                         (int)sizeof(Smem));
    qsim_kernel<<<B, NT, sizeof(Smem)>>>(cp, p, out);
}